// round 15
// baseline (speedup 1.0000x reference)
#include <cuda_runtime.h>
#include <math.h>

#define Bq 8
#define Tq 4096
#define Dq 768
#define Hq 12
#define HDq 64
#define Kq 32
#define NSEG 16
#define MROWS 256   // B*K

typedef unsigned long long ull;

// ---------- scratch ----------
__device__ float g_part[(size_t)NSEG * MROWS * Dq];
__device__ float g_xs  [(size_t)MROWS * Dq];
__device__ float g_qkv [(size_t)MROWS * 3 * Dq];
__device__ float g_vs  [(size_t)MROWS * Dq];
__device__ float g_y   [(size_t)3 * MROWS * Dq];   // split-k partials
__device__ float g_ysum[(size_t)MROWS * Dq];

// ---------- packed f32x2 helpers ----------
__device__ __forceinline__ ull ffma2(ull a, ull b, ull c) {
    ull d;
    asm("fma.rn.f32x2 %0, %1, %2, %3;" : "=l"(d) : "l"(a), "l"(b), "l"(c));
    return d;
}
__device__ __forceinline__ ull fadd2(ull a, ull b) {
    ull d;
    asm("add.rn.f32x2 %0, %1, %2;" : "=l"(d) : "l"(a), "l"(b));
    return d;
}
__device__ __forceinline__ ull pack2(float v) {
    ull r; unsigned u = __float_as_uint(v);
    asm("mov.b64 %0, {%1, %2};" : "=l"(r) : "r"(u), "r"(u));
    return r;
}

__global__ void kprobe() {}

// ======================================================================
// kA (R9-exact, 59us known-good): partial xs[seg][b,k,d]
// 768 thr = (dq 0..191 d-quad) x (kh 0..3, 8 k each). acc = 16 ull.
// ======================================================================
__global__ __launch_bounds__(768, 1) void kA(const float* __restrict__ x,
                                             const float* __restrict__ basis) {
    const int b = blockIdx.y, seg = blockIdx.x;
    const int tid = threadIdx.x;
    const int dq = tid % 192;
    const int kh = tid / 192;          // warp-uniform
    __shared__ ull sb[64][Kq];

    ull acc[16];
#pragma unroll
    for (int i = 0; i < 16; ++i) acc[i] = 0ull;

    const int t0 = seg * 256;          // TSEG = 256
    const ulonglong2* x4 = (const ulonglong2*)x + (size_t)b * Tq * 192;

    ulonglong2 xr[2];
    xr[0] = x4[(size_t)t0 * 192 + dq];
    xr[1] = x4[(size_t)(t0 + 1) * 192 + dq];

    for (int tile = 0; tile < 4; ++tile) {
        const int tb = t0 + tile * 64;
        __syncthreads();
#pragma unroll
        for (int i = 0; i < 3; ++i) {
            int idx = tid + i * 768;
            if (idx < 2048) {
                int tt = idx >> 5, k = idx & 31;
                sb[tt][k] = pack2(basis[((size_t)b * Tq + tb + tt) * Kq + k]);
            }
        }
        __syncthreads();
#pragma unroll 4
        for (int t2 = 0; t2 < 32; ++t2) {
#pragma unroll
            for (int j = 0; j < 2; ++j) {
                const int tt = t2 * 2 + j;
                ulonglong2 xv = xr[j];
                int tpf = tb + tt + 2;
                if (tpf > t0 + 255) tpf = t0 + 255;
                xr[j] = x4[(size_t)tpf * 192 + dq];
                const ulonglong2* bp = (const ulonglong2*)&sb[tt][kh * 8];
#pragma unroll
                for (int kk2 = 0; kk2 < 4; ++kk2) {
                    ulonglong2 bb = bp[kk2];
                    acc[kk2 * 2]         = ffma2(xv.x, bb.x, acc[kk2 * 2]);
                    acc[kk2 * 2 + 1]     = ffma2(xv.x, bb.y, acc[kk2 * 2 + 1]);
                    acc[8 + kk2 * 2]     = ffma2(xv.y, bb.x, acc[8 + kk2 * 2]);
                    acc[8 + kk2 * 2 + 1] = ffma2(xv.y, bb.y, acc[8 + kk2 * 2 + 1]);
                }
            }
        }
    }
    ulonglong2* po = (ulonglong2*)g_part;
#pragma unroll
    for (int kk = 0; kk < 8; ++kk) {
        int k = kh * 8 + kk;
        ulonglong2 r; r.x = acc[kk]; r.y = acc[8 + kk];
        po[((size_t)seg * MROWS + b * Kq + k) * 192 + dq] = r;
    }
}

// ======================================================================
// kA2: reduce NSEG partials -> g_xs
// ======================================================================
__global__ void kA2() {
    const int j = blockIdx.x * 256 + threadIdx.x;
    const float4* p = (const float4*)g_part;
    float4 s = p[j];
#pragma unroll
    for (int seg = 1; seg < NSEG; ++seg) {
        float4 v = p[(size_t)seg * (MROWS * Dq / 4) + j];
        s.x += v.x; s.y += v.y; s.z += v.z; s.w += v.w;
    }
    ((float4*)g_xs)[j] = s;
}

// ======================================================================
// GEMM  C[M=256,N] = A[256,768] * W[N,768]^T  (K range via blockIdx.z)
// ======================================================================
__global__ __launch_bounds__(256, 2) void kgemm(const float* __restrict__ Wm,
                                                int N, int mode, int ks) {
    const int z = blockIdx.z;
    const float* Am = (mode == 0) ? g_xs : g_vs;
    float*       Cm = (mode == 0) ? g_qkv : (g_y + (size_t)z * MROWS * Dq);

    __shared__ __align__(16) ull   Asu[16][64];
    __shared__ __align__(16) float Bs [16][64];

    const int tid = threadIdx.x;
    const int bm = blockIdx.y * 64, bn = blockIdx.x * 64;
    const int tm = (tid >> 4) << 2, tn = (tid & 15) << 2;
    const int k0 = z * ks, k1 = k0 + ks;

    ull acc[4][2];
#pragma unroll
    for (int i = 0; i < 4; ++i) { acc[i][0] = 0ull; acc[i][1] = 0ull; }

    const int lrow = tid >> 2;
    const int lq   = (tid & 3) << 2;
    const float* Ag = Am + (size_t)(bm + lrow) * 768 + lq;
    const float* Bg = Wm + (size_t)(bn + lrow) * 768 + lq;

    float4 av = *(const float4*)(Ag + k0);
    float4 bv = *(const float4*)(Bg + k0);

    for (int kt = k0; kt < k1; kt += 16) {
        __syncthreads();
        Asu[lq + 0][lrow] = pack2(av.x); Asu[lq + 1][lrow] = pack2(av.y);
        Asu[lq + 2][lrow] = pack2(av.z); Asu[lq + 3][lrow] = pack2(av.w);
        Bs[lq + 0][lrow] = bv.x; Bs[lq + 1][lrow] = bv.y;
        Bs[lq + 2][lrow] = bv.z; Bs[lq + 3][lrow] = bv.w;
        __syncthreads();
        if (kt + 16 < k1) {
            av = *(const float4*)(Ag + kt + 16);
            bv = *(const float4*)(Bg + kt + 16);
        }
#pragma unroll
        for (int k = 0; k < 16; ++k) {
            ulonglong2 a01 = *(const ulonglong2*)&Asu[k][tm];
            ulonglong2 a23 = *(const ulonglong2*)&Asu[k][tm + 2];
            ulonglong2 bf  = *(const ulonglong2*)&Bs[k][tn];
            acc[0][0] = ffma2(a01.x, bf.x, acc[0][0]); acc[0][1] = ffma2(a01.x, bf.y, acc[0][1]);
            acc[1][0] = ffma2(a01.y, bf.x, acc[1][0]); acc[1][1] = ffma2(a01.y, bf.y, acc[1][1]);
            acc[2][0] = ffma2(a23.x, bf.x, acc[2][0]); acc[2][1] = ffma2(a23.x, bf.y, acc[2][1]);
            acc[3][0] = ffma2(a23.y, bf.x, acc[3][0]); acc[3][1] = ffma2(a23.y, bf.y, acc[3][1]);
        }
    }
#pragma unroll
    for (int i = 0; i < 4; ++i) {
        ulonglong2 r; r.x = acc[i][0]; r.y = acc[i][1];
        *(ulonglong2*)(Cm + (size_t)(bm + tm + i) * N + bn + tn) = r;
    }
}

// ======================================================================
// FHN: one warp per (m,h)
// ======================================================================
__global__ __launch_bounds__(256) void kfhn(const float* __restrict__ sfilt) {
    const int gw = blockIdx.x * 8 + (threadIdx.x >> 5);
    const int h = gw % Hq;
    const int m = gw / Hq;
    const int k = m & 31;
    const int l = threadIdx.x & 31;
    const float* row = g_qkv + (size_t)m * (3 * Dq);

    float q0 = row[h * HDq + l],      q1 = row[h * HDq + l + 32];
    float c0 = row[Dq + h * HDq + l], c1 = row[Dq + h * HDq + l + 32];
    float p = q0 * c0 + q1 * c1;
#pragma unroll
    for (int o = 16; o; o >>= 1) p += __shfl_xor_sync(0xffffffffu, p, o);

    float dot  = p * 0.125f;
    float fl   = 1.f / (1.f + expf(-sfilt[h * 32 + k]));
    float stim = dot * fl;
    float as    = fabsf(stim);
    float scale = fmaxf(as, 1e-6f);
    float sn    = stim / scale;
    float gate  = 1.f / (1.f + expf(-(as - 0.5f) * 10.f));
    float I     = sn * (0.1f + 0.9f * gate);
    const float alpha = 0.08f, denom = 1.064f;
    float v = 0.f, w = 0.f;
#pragma unroll
    for (int it = 0; it < 2; ++it) {
        float dv = v - (v * v * v) / 3.0f - w + I;
        float vn = v + dv;
        float wn = (w + (vn + 0.7f) * alpha) / denom;
        v = fminf(fmaxf(vn, -3.f), 3.f);
        w = fminf(fmaxf(wn, -3.f), 3.f);
    }
    float sf = v * scale;

    g_vs[(size_t)m * Dq + h * HDq + l]      = sf * row[2 * Dq + h * HDq + l];
    g_vs[(size_t)m * Dq + h * HDq + l + 32] = sf * row[2 * Dq + h * HDq + l + 32];
}

// ======================================================================
// kyr: sum 3 split-k partials -> g_ysum
// ======================================================================
__global__ void kyr() {
    const int j = blockIdx.x * 256 + threadIdx.x;
    const float4* p = (const float4*)g_y;
    float4 a = p[j], bb = p[j + MROWS * Dq / 4], c = p[j + 2 * (MROWS * Dq / 4)];
    float4 s; s.x = a.x + bb.x + c.x; s.y = a.y + bb.y + c.y;
    s.z = a.z + bb.z + c.z; s.w = a.w + bb.w + c.w;
    ((float4*)g_ysum)[j] = s;
}

// ======================================================================
// kC: out[b][t,d] = sum_k basis[b][t,k] * ysum[b*32+k,d]
// Tile 64t x 64d, 6144 blocks (~41/SM -> balanced), 128 thr,
// microtile 4t x 8d (4 pairs). ~7 blocks/SM resident.
// ======================================================================
__global__ __launch_bounds__(128) void kC(const float* __restrict__ basis,
                                          float* __restrict__ out) {
    const int bn = blockIdx.x * 64;    // d
    const int bt = blockIdx.y * 64;    // t
    const int b  = blockIdx.z;
    const int tid = threadIdx.x;
    const int tr = tid >> 3;           // 0..15 -> t rows tr*4..tr*4+3
    const int tc = tid & 7;            // 0..7  -> d pairs tc*4..tc*4+3

    __shared__ __align__(16) ull sA[Kq][64];   // [k][t] packed basis
    __shared__ __align__(16) ull sB[Kq][32];   // [k][d-pair] packed y

    // fill sA: 64 t-rows x 8 k-quads, 512 float4 / 128 thr = 4 each
#pragma unroll
    for (int i = 0; i < 4; ++i) {
        int idx = tid + i * 128;
        int row = idx >> 3, c4 = idx & 7;
        float4 f = *(const float4*)&basis[((size_t)b * Tq + bt + row) * Kq + c4 * 4];
        sA[c4 * 4 + 0][row] = pack2(f.x);
        sA[c4 * 4 + 1][row] = pack2(f.y);
        sA[c4 * 4 + 2][row] = pack2(f.z);
        sA[c4 * 4 + 3][row] = pack2(f.w);
    }
    // fill sB: 32 k x 16 quad-groups (64 floats), 512 idx / 128 thr = 4 each
#pragma unroll
    for (int i = 0; i < 4; ++i) {
        int idx = tid + i * 128;
        int k = idx >> 4, g = idx & 15;       // g = 4-float group
        ulonglong2 v = *(const ulonglong2*)&g_ysum[(size_t)(b * Kq + k) * Dq + bn + g * 4];
        sB[k][g * 2]     = v.x;
        sB[k][g * 2 + 1] = v.y;
    }
    __syncthreads();

    ull acc[4][4];
#pragma unroll
    for (int i = 0; i < 4; ++i)
#pragma unroll
        for (int j = 0; j < 4; ++j) acc[i][j] = 0ull;

#pragma unroll
    for (int k = 0; k < Kq; ++k) {
        ulonglong2 a01 = *(const ulonglong2*)&sA[k][tr * 4];
        ulonglong2 a23 = *(const ulonglong2*)&sA[k][tr * 4 + 2];
        ulonglong2 b01 = *(const ulonglong2*)&sB[k][tc * 4];
        ulonglong2 b23 = *(const ulonglong2*)&sB[k][tc * 4 + 2];
        ull a[4] = {a01.x, a01.y, a23.x, a23.y};
#pragma unroll
        for (int i = 0; i < 4; ++i) {
            acc[i][0] = ffma2(a[i], b01.x, acc[i][0]);
            acc[i][1] = ffma2(a[i], b01.y, acc[i][1]);
            acc[i][2] = ffma2(a[i], b23.x, acc[i][2]);
            acc[i][3] = ffma2(a[i], b23.y, acc[i][3]);
        }
    }

#pragma unroll
    for (int i = 0; i < 4; ++i) {
        float* base = out + ((size_t)b * Tq + bt + tr * 4 + i) * Dq + bn + tc * 8;
        ulonglong2 r0; r0.x = acc[i][0]; r0.y = acc[i][1];
        ulonglong2 r1; r1.x = acc[i][2]; r1.y = acc[i][3];
        *(ulonglong2*)(base)     = r0;
        *(ulonglong2*)(base + 4) = r1;
    }
}

// ======================================================================
extern "C" void kernel_launch(void* const* d_in, const int* in_sizes, int n_in,
                              void* d_out, int out_size) {
    const float* x     = (const float*)d_in[0];
    const float* basis = (const float*)d_in[1];
    const float* wqkv  = (const float*)d_in[2];
    const float* wout  = (const float*)d_in[3];
    const float* sfilt = (const float*)d_in[4];
    float* out = (float*)d_out;

    kprobe<<<1, 1>>>();
    kA  <<<dim3(NSEG, Bq), 768>>>(x, basis);
    kA2 <<<(MROWS * Dq / 4) / 256, 256>>>();
    kgemm<<<dim3(2304 / 64, MROWS / 64, 1), 256>>>(wqkv, 3 * Dq, 0, 768);  // captured
    kfhn<<<3072 / 8, 256>>>(sfilt);
    kgemm<<<dim3(768 / 64, MROWS / 64, 3), 256>>>(wout, Dq, 1, 256);
    kyr <<<(MROWS * Dq / 4) / 256, 256>>>();
    kC  <<<dim3(Dq / 64, Tq / 64, Bq), 128>>>(basis, out);
}

// round 16
// speedup vs baseline: 1.2389x; 1.2389x over previous
#include <cuda_runtime.h>
#include <math.h>

#define Bq 8
#define Tq 4096
#define Dq 768
#define Hq 12
#define HDq 64
#define Kq 32
#define NSEG 16
#define MROWS 256   // B*K
#define QKV_STRIDE ((size_t)MROWS * 3 * Dq)

typedef unsigned long long ull;

// ---------- scratch ----------
__device__ float g_part[(size_t)NSEG * MROWS * Dq];
__device__ float g_xs  [(size_t)MROWS * Dq];
__device__ float g_qkv [(size_t)2 * MROWS * 3 * Dq];  // 2 split-k partials
__device__ float g_vs  [(size_t)MROWS * Dq];
__device__ float g_y   [(size_t)3 * MROWS * Dq];      // split-k partials
__device__ float g_ysum[(size_t)MROWS * Dq];

// ---------- packed f32x2 helpers ----------
__device__ __forceinline__ ull ffma2(ull a, ull b, ull c) {
    ull d;
    asm("fma.rn.f32x2 %0, %1, %2, %3;" : "=l"(d) : "l"(a), "l"(b), "l"(c));
    return d;
}
__device__ __forceinline__ ull fadd2(ull a, ull b) {
    ull d;
    asm("add.rn.f32x2 %0, %1, %2;" : "=l"(d) : "l"(a), "l"(b));
    return d;
}
__device__ __forceinline__ ull pack2(float v) {
    ull r; unsigned u = __float_as_uint(v);
    asm("mov.b64 %0, {%1, %2};" : "=l"(r) : "r"(u), "r"(u));
    return r;
}

__global__ void kprobe() {}

// ======================================================================
// kA (R9-exact, 59us known-good): partial xs[seg][b,k,d]
// ======================================================================
__global__ __launch_bounds__(768, 1) void kA(const float* __restrict__ x,
                                             const float* __restrict__ basis) {
    const int b = blockIdx.y, seg = blockIdx.x;
    const int tid = threadIdx.x;
    const int dq = tid % 192;
    const int kh = tid / 192;          // warp-uniform
    __shared__ ull sb[64][Kq];

    ull acc[16];
#pragma unroll
    for (int i = 0; i < 16; ++i) acc[i] = 0ull;

    const int t0 = seg * 256;          // TSEG = 256
    const ulonglong2* x4 = (const ulonglong2*)x + (size_t)b * Tq * 192;

    ulonglong2 xr[2];
    xr[0] = x4[(size_t)t0 * 192 + dq];
    xr[1] = x4[(size_t)(t0 + 1) * 192 + dq];

    for (int tile = 0; tile < 4; ++tile) {
        const int tb = t0 + tile * 64;
        __syncthreads();
#pragma unroll
        for (int i = 0; i < 3; ++i) {
            int idx = tid + i * 768;
            if (idx < 2048) {
                int tt = idx >> 5, k = idx & 31;
                sb[tt][k] = pack2(basis[((size_t)b * Tq + tb + tt) * Kq + k]);
            }
        }
        __syncthreads();
#pragma unroll 4
        for (int t2 = 0; t2 < 32; ++t2) {
#pragma unroll
            for (int j = 0; j < 2; ++j) {
                const int tt = t2 * 2 + j;
                ulonglong2 xv = xr[j];
                int tpf = tb + tt + 2;
                if (tpf > t0 + 255) tpf = t0 + 255;
                xr[j] = x4[(size_t)tpf * 192 + dq];
                const ulonglong2* bp = (const ulonglong2*)&sb[tt][kh * 8];
#pragma unroll
                for (int kk2 = 0; kk2 < 4; ++kk2) {
                    ulonglong2 bb = bp[kk2];
                    acc[kk2 * 2]         = ffma2(xv.x, bb.x, acc[kk2 * 2]);
                    acc[kk2 * 2 + 1]     = ffma2(xv.x, bb.y, acc[kk2 * 2 + 1]);
                    acc[8 + kk2 * 2]     = ffma2(xv.y, bb.x, acc[8 + kk2 * 2]);
                    acc[8 + kk2 * 2 + 1] = ffma2(xv.y, bb.y, acc[8 + kk2 * 2 + 1]);
                }
            }
        }
    }
    ulonglong2* po = (ulonglong2*)g_part;
#pragma unroll
    for (int kk = 0; kk < 8; ++kk) {
        int k = kh * 8 + kk;
        ulonglong2 r; r.x = acc[kk]; r.y = acc[8 + kk];
        po[((size_t)seg * MROWS + b * Kq + k) * 192 + dq] = r;
    }
}

// ======================================================================
// kA2: reduce NSEG partials -> g_xs
// ======================================================================
__global__ void kA2() {
    const int j = blockIdx.x * 256 + threadIdx.x;
    const float4* p = (const float4*)g_part;
    float4 s = p[j];
#pragma unroll
    for (int seg = 1; seg < NSEG; ++seg) {
        float4 v = p[(size_t)seg * (MROWS * Dq / 4) + j];
        s.x += v.x; s.y += v.y; s.z += v.z; s.w += v.w;
    }
    ((float4*)g_xs)[j] = s;
}

// ======================================================================
// GEMM  C[M=256,N] = A[256,768] * W[N,768]^T  (K range via blockIdx.z)
// mode 0: g_xs -> g_qkv + z*QKV_STRIDE (2-way split-K)
// mode 1: g_vs -> g_y + z*MROWS*Dq     (3-way split-K)
// ======================================================================
__global__ __launch_bounds__(256, 2) void kgemm(const float* __restrict__ Wm,
                                                int N, int mode, int ks) {
    const int z = blockIdx.z;
    const float* Am = (mode == 0) ? g_xs : g_vs;
    float*       Cm = (mode == 0) ? (g_qkv + (size_t)z * QKV_STRIDE)
                                  : (g_y + (size_t)z * MROWS * Dq);

    __shared__ __align__(16) ull   Asu[16][64];
    __shared__ __align__(16) float Bs [16][64];

    const int tid = threadIdx.x;
    const int bm = blockIdx.y * 64, bn = blockIdx.x * 64;
    const int tm = (tid >> 4) << 2, tn = (tid & 15) << 2;
    const int k0 = z * ks, k1 = k0 + ks;

    ull acc[4][2];
#pragma unroll
    for (int i = 0; i < 4; ++i) { acc[i][0] = 0ull; acc[i][1] = 0ull; }

    const int lrow = tid >> 2;
    const int lq   = (tid & 3) << 2;
    const float* Ag = Am + (size_t)(bm + lrow) * 768 + lq;
    const float* Bg = Wm + (size_t)(bn + lrow) * 768 + lq;

    float4 av = *(const float4*)(Ag + k0);
    float4 bv = *(const float4*)(Bg + k0);

    for (int kt = k0; kt < k1; kt += 16) {
        __syncthreads();
        Asu[lq + 0][lrow] = pack2(av.x); Asu[lq + 1][lrow] = pack2(av.y);
        Asu[lq + 2][lrow] = pack2(av.z); Asu[lq + 3][lrow] = pack2(av.w);
        Bs[lq + 0][lrow] = bv.x; Bs[lq + 1][lrow] = bv.y;
        Bs[lq + 2][lrow] = bv.z; Bs[lq + 3][lrow] = bv.w;
        __syncthreads();
        if (kt + 16 < k1) {
            av = *(const float4*)(Ag + kt + 16);
            bv = *(const float4*)(Bg + kt + 16);
        }
#pragma unroll
        for (int k = 0; k < 16; ++k) {
            ulonglong2 a01 = *(const ulonglong2*)&Asu[k][tm];
            ulonglong2 a23 = *(const ulonglong2*)&Asu[k][tm + 2];
            ulonglong2 bf  = *(const ulonglong2*)&Bs[k][tn];
            acc[0][0] = ffma2(a01.x, bf.x, acc[0][0]); acc[0][1] = ffma2(a01.x, bf.y, acc[0][1]);
            acc[1][0] = ffma2(a01.y, bf.x, acc[1][0]); acc[1][1] = ffma2(a01.y, bf.y, acc[1][1]);
            acc[2][0] = ffma2(a23.x, bf.x, acc[2][0]); acc[2][1] = ffma2(a23.x, bf.y, acc[2][1]);
            acc[3][0] = ffma2(a23.y, bf.x, acc[3][0]); acc[3][1] = ffma2(a23.y, bf.y, acc[3][1]);
        }
    }
#pragma unroll
    for (int i = 0; i < 4; ++i) {
        ulonglong2 r; r.x = acc[i][0]; r.y = acc[i][1];
        *(ulonglong2*)(Cm + (size_t)(bm + tm + i) * N + bn + tn) = r;
    }
}

// ======================================================================
// FHN: one warp per (m,h); sums the 2 gemm0 split-K partials inline.
// ======================================================================
__global__ __launch_bounds__(256) void kfhn(const float* __restrict__ sfilt) {
    const int gw = blockIdx.x * 8 + (threadIdx.x >> 5);
    const int h = gw % Hq;
    const int m = gw / Hq;
    const int k = m & 31;
    const int l = threadIdx.x & 31;
    const float* r0 = g_qkv + (size_t)m * (3 * Dq);
    const float* r1 = r0 + QKV_STRIDE;

    float q0 = r0[h * HDq + l]      + r1[h * HDq + l];
    float q1 = r0[h * HDq + l + 32] + r1[h * HDq + l + 32];
    float c0 = r0[Dq + h * HDq + l]      + r1[Dq + h * HDq + l];
    float c1 = r0[Dq + h * HDq + l + 32] + r1[Dq + h * HDq + l + 32];
    float p = q0 * c0 + q1 * c1;
#pragma unroll
    for (int o = 16; o; o >>= 1) p += __shfl_xor_sync(0xffffffffu, p, o);

    float dot  = p * 0.125f;
    float fl   = 1.f / (1.f + expf(-sfilt[h * 32 + k]));
    float stim = dot * fl;
    float as    = fabsf(stim);
    float scale = fmaxf(as, 1e-6f);
    float sn    = stim / scale;
    float gate  = 1.f / (1.f + expf(-(as - 0.5f) * 10.f));
    float I     = sn * (0.1f + 0.9f * gate);
    const float alpha = 0.08f, denom = 1.064f;
    float v = 0.f, w = 0.f;
#pragma unroll
    for (int it = 0; it < 2; ++it) {
        float dv = v - (v * v * v) / 3.0f - w + I;
        float vn = v + dv;
        float wn = (w + (vn + 0.7f) * alpha) / denom;
        v = fminf(fmaxf(vn, -3.f), 3.f);
        w = fminf(fmaxf(wn, -3.f), 3.f);
    }
    float sf = v * scale;

    float v0 = r0[2 * Dq + h * HDq + l]      + r1[2 * Dq + h * HDq + l];
    float v1 = r0[2 * Dq + h * HDq + l + 32] + r1[2 * Dq + h * HDq + l + 32];
    g_vs[(size_t)m * Dq + h * HDq + l]      = sf * v0;
    g_vs[(size_t)m * Dq + h * HDq + l + 32] = sf * v1;
}

// ======================================================================
// kyr: sum 3 split-k partials -> g_ysum
// ======================================================================
__global__ void kyr() {
    const int j = blockIdx.x * 256 + threadIdx.x;
    const float4* p = (const float4*)g_y;
    float4 a = p[j], bb = p[j + MROWS * Dq / 4], c = p[j + 2 * (MROWS * Dq / 4)];
    float4 s; s.x = a.x + bb.x + c.x; s.y = a.y + bb.y + c.y;
    s.z = a.z + bb.z + c.z; s.w = a.w + bb.w + c.w;
    ((float4*)g_ysum)[j] = s;
}

// ======================================================================
// kC (R9-exact): out[b][t,d] = sum_k basis[b][t,k] * ysum[b*32+k,d]
// Tile 64t x 128d, 128 thr, microtile 4t x 16d. Pad 66 (even).
// ======================================================================
__global__ __launch_bounds__(128) void kC(const float* __restrict__ basis,
                                          float* __restrict__ out) {
    const int bn = blockIdx.x * 128;   // d
    const int bt = blockIdx.y * 64;    // t
    const int b  = blockIdx.z;
    const int tid = threadIdx.x;
    const int tr = tid >> 3;           // 0..15 -> t = tr*4
    const int tc = tid & 7;            // 0..7  -> d groups tc*4 + j*32

    __shared__ __align__(16) ull sA[32][66];
    __shared__ __align__(16) ull sB[32][66];

#pragma unroll
    for (int i = 0; i < 4; ++i) {
        int idx = tid + i * 128;
        int row = idx >> 3, c4 = idx & 7;
        float4 f = *(const float4*)&basis[((size_t)b * Tq + bt + row) * Kq + c4 * 4];
        sA[c4 * 4 + 0][row] = pack2(f.x);
        sA[c4 * 4 + 1][row] = pack2(f.y);
        sA[c4 * 4 + 2][row] = pack2(f.z);
        sA[c4 * 4 + 3][row] = pack2(f.w);
    }
#pragma unroll
    for (int i = 0; i < 8; ++i) {
        int idx = tid + i * 128;
        int k = idx >> 5, g = idx & 31;
        ulonglong2 v = *(const ulonglong2*)&g_ysum[(size_t)(b * Kq + k) * Dq + bn + g * 4];
        sB[k][g * 2]     = v.x;
        sB[k][g * 2 + 1] = v.y;
    }
    __syncthreads();

    ull acc[4][8];
#pragma unroll
    for (int i = 0; i < 4; ++i)
#pragma unroll
        for (int j = 0; j < 8; ++j) acc[i][j] = 0ull;

#pragma unroll
    for (int k = 0; k < 32; ++k) {
        ulonglong2 a01 = *(const ulonglong2*)&sA[k][tr * 4];
        ulonglong2 a23 = *(const ulonglong2*)&sA[k][tr * 4 + 2];
        ulonglong2 b0 = *(const ulonglong2*)&sB[k][tc * 2];
        ulonglong2 b1 = *(const ulonglong2*)&sB[k][tc * 2 + 16];
        ulonglong2 b2 = *(const ulonglong2*)&sB[k][tc * 2 + 32];
        ulonglong2 b3 = *(const ulonglong2*)&sB[k][tc * 2 + 48];
        ull a[4] = {a01.x, a01.y, a23.x, a23.y};
#pragma unroll
        for (int i = 0; i < 4; ++i) {
            acc[i][0] = ffma2(a[i], b0.x, acc[i][0]);
            acc[i][1] = ffma2(a[i], b0.y, acc[i][1]);
            acc[i][2] = ffma2(a[i], b1.x, acc[i][2]);
            acc[i][3] = ffma2(a[i], b1.y, acc[i][3]);
            acc[i][4] = ffma2(a[i], b2.x, acc[i][4]);
            acc[i][5] = ffma2(a[i], b2.y, acc[i][5]);
            acc[i][6] = ffma2(a[i], b3.x, acc[i][6]);
            acc[i][7] = ffma2(a[i], b3.y, acc[i][7]);
        }
    }

#pragma unroll
    for (int i = 0; i < 4; ++i) {
        float* base = out + ((size_t)b * Tq + bt + tr * 4 + i) * Dq + bn + tc * 4;
#pragma unroll
        for (int j = 0; j < 4; ++j) {
            ulonglong2 r; r.x = acc[i][2 * j]; r.y = acc[i][2 * j + 1];
            *(ulonglong2*)(base + j * 32) = r;
        }
    }
}

// ======================================================================
extern "C" void kernel_launch(void* const* d_in, const int* in_sizes, int n_in,
                              void* d_out, int out_size) {
    const float* x     = (const float*)d_in[0];
    const float* basis = (const float*)d_in[1];
    const float* wqkv  = (const float*)d_in[2];
    const float* wout  = (const float*)d_in[3];
    const float* sfilt = (const float*)d_in[4];
    float* out = (float*)d_out;

    kprobe<<<1, 1>>>();
    kA  <<<dim3(NSEG, Bq), 768>>>(x, basis);
    kA2 <<<(MROWS * Dq / 4) / 256, 256>>>();
    kgemm<<<dim3(2304 / 64, MROWS / 64, 2), 256>>>(wqkv, 3 * Dq, 0, 384);  // captured
    kfhn<<<3072 / 8, 256>>>(sfilt);
    kgemm<<<dim3(768 / 64, MROWS / 64, 3), 256>>>(wout, Dq, 1, 256);
    kyr <<<(MROWS * Dq / 4) / 256, 256>>>();
    kC  <<<dim3(Dq / 128, Tq / 64, Bq), 128>>>(basis, out);
}

// round 17
// speedup vs baseline: 1.2589x; 1.0162x over previous
#include <cuda_runtime.h>
#include <math.h>

#define Bq 8
#define Tq 4096
#define Dq 768
#define Hq 12
#define HDq 64
#define Kq 32
#define NSEG 16
#define MROWS 256   // B*K
#define QKV_STRIDE ((size_t)MROWS * 3 * Dq)
#define YSPLIT 6

typedef unsigned long long ull;

// ---------- scratch ----------
__device__ float g_part[(size_t)NSEG * MROWS * Dq];
__device__ float g_xs  [(size_t)MROWS * Dq];
__device__ float g_qkv [(size_t)2 * MROWS * 3 * Dq];     // 2 split-k partials
__device__ float g_vs  [(size_t)MROWS * Dq];
__device__ float g_y   [(size_t)YSPLIT * MROWS * Dq];    // split-k partials
__device__ float g_ysum[(size_t)MROWS * Dq];

// ---------- packed f32x2 helpers ----------
__device__ __forceinline__ ull ffma2(ull a, ull b, ull c) {
    ull d;
    asm("fma.rn.f32x2 %0, %1, %2, %3;" : "=l"(d) : "l"(a), "l"(b), "l"(c));
    return d;
}
__device__ __forceinline__ ull fadd2(ull a, ull b) {
    ull d;
    asm("add.rn.f32x2 %0, %1, %2;" : "=l"(d) : "l"(a), "l"(b));
    return d;
}
__device__ __forceinline__ ull pack2(float v) {
    ull r; unsigned u = __float_as_uint(v);
    asm("mov.b64 %0, {%1, %2};" : "=l"(r) : "r"(u), "r"(u));
    return r;
}

__global__ void kprobe() {}

// ======================================================================
// kA (R9-exact, 59us known-good): partial xs[seg][b,k,d]
// ======================================================================
__global__ __launch_bounds__(768, 1) void kA(const float* __restrict__ x,
                                             const float* __restrict__ basis) {
    const int b = blockIdx.y, seg = blockIdx.x;
    const int tid = threadIdx.x;
    const int dq = tid % 192;
    const int kh = tid / 192;          // warp-uniform
    __shared__ ull sb[64][Kq];

    ull acc[16];
#pragma unroll
    for (int i = 0; i < 16; ++i) acc[i] = 0ull;

    const int t0 = seg * 256;          // TSEG = 256
    const ulonglong2* x4 = (const ulonglong2*)x + (size_t)b * Tq * 192;

    ulonglong2 xr[2];
    xr[0] = x4[(size_t)t0 * 192 + dq];
    xr[1] = x4[(size_t)(t0 + 1) * 192 + dq];

    for (int tile = 0; tile < 4; ++tile) {
        const int tb = t0 + tile * 64;
        __syncthreads();
#pragma unroll
        for (int i = 0; i < 3; ++i) {
            int idx = tid + i * 768;
            if (idx < 2048) {
                int tt = idx >> 5, k = idx & 31;
                sb[tt][k] = pack2(basis[((size_t)b * Tq + tb + tt) * Kq + k]);
            }
        }
        __syncthreads();
#pragma unroll 4
        for (int t2 = 0; t2 < 32; ++t2) {
#pragma unroll
            for (int j = 0; j < 2; ++j) {
                const int tt = t2 * 2 + j;
                ulonglong2 xv = xr[j];
                int tpf = tb + tt + 2;
                if (tpf > t0 + 255) tpf = t0 + 255;
                xr[j] = x4[(size_t)tpf * 192 + dq];
                const ulonglong2* bp = (const ulonglong2*)&sb[tt][kh * 8];
#pragma unroll
                for (int kk2 = 0; kk2 < 4; ++kk2) {
                    ulonglong2 bb = bp[kk2];
                    acc[kk2 * 2]         = ffma2(xv.x, bb.x, acc[kk2 * 2]);
                    acc[kk2 * 2 + 1]     = ffma2(xv.x, bb.y, acc[kk2 * 2 + 1]);
                    acc[8 + kk2 * 2]     = ffma2(xv.y, bb.x, acc[8 + kk2 * 2]);
                    acc[8 + kk2 * 2 + 1] = ffma2(xv.y, bb.y, acc[8 + kk2 * 2 + 1]);
                }
            }
        }
    }
    ulonglong2* po = (ulonglong2*)g_part;
#pragma unroll
    for (int kk = 0; kk < 8; ++kk) {
        int k = kh * 8 + kk;
        ulonglong2 r; r.x = acc[kk]; r.y = acc[8 + kk];
        po[((size_t)seg * MROWS + b * Kq + k) * 192 + dq] = r;
    }
}

// ======================================================================
// kA2: reduce NSEG partials -> g_xs
// ======================================================================
__global__ void kA2() {
    const int j = blockIdx.x * 256 + threadIdx.x;
    const float4* p = (const float4*)g_part;
    float4 s = p[j];
#pragma unroll
    for (int seg = 1; seg < NSEG; ++seg) {
        float4 v = p[(size_t)seg * (MROWS * Dq / 4) + j];
        s.x += v.x; s.y += v.y; s.z += v.z; s.w += v.w;
    }
    ((float4*)g_xs)[j] = s;
}

// ======================================================================
// kgemm v2: C[M=256,N] = A[256,768] * W[N,768]^T  (K range via blockIdx.z)
// Tile 128m x 64n, 128 thr, microtile 8m x 8n: per k-step
// 6 LDS.128 + 32 FFMA2 per thread -> FMA-bound (old 4x4 was LDS-bound).
// mode 0: g_xs -> g_qkv + z*QKV_STRIDE ; mode 1: g_vs -> g_y + z*MROWS*Dq
// ======================================================================
__global__ __launch_bounds__(128, 2) void kgemm(const float* __restrict__ Wm,
                                                int N, int mode, int ks) {
    const int z = blockIdx.z;
    const float* Am = (mode == 0) ? g_xs : g_vs;
    float*       Cm = (mode == 0) ? (g_qkv + (size_t)z * QKV_STRIDE)
                                  : (g_y + (size_t)z * MROWS * Dq);

    __shared__ __align__(16) ull   Asu[16][128];   // pack2(A[m][k]) at [k][m]
    __shared__ __align__(16) float Bs [16][64];    // W[n][k] at [k][n]

    const int tid = threadIdx.x;
    const int bm = blockIdx.y * 128, bn = blockIdx.x * 64;
    const int tm = (tid >> 3) * 8;     // m ull-offset 0..120
    const int tn = (tid & 7) * 8;      // n float-offset 0..56
    const int k0 = z * ks;

    ull acc[8][4];
#pragma unroll
    for (int i = 0; i < 8; ++i)
#pragma unroll
        for (int j = 0; j < 4; ++j) acc[i][j] = 0ull;

    const float* Ag = Am + (size_t)(bm + tid) * 768 + k0;      // one A row/thread
    const int brow = tid >> 1, bq = (tid & 1) * 8;             // B row + k-half
    const float* Bg = Wm + (size_t)(bn + brow) * 768 + k0 + bq;

    float4 av[4], bv[2];
#pragma unroll
    for (int q = 0; q < 4; ++q) av[q] = *(const float4*)(Ag + q * 4);
    bv[0] = *(const float4*)(Bg);
    bv[1] = *(const float4*)(Bg + 4);

    for (int kt = 0; kt < ks; kt += 16) {
        __syncthreads();
#pragma unroll
        for (int q = 0; q < 4; ++q) {
            Asu[q * 4 + 0][tid] = pack2(av[q].x);
            Asu[q * 4 + 1][tid] = pack2(av[q].y);
            Asu[q * 4 + 2][tid] = pack2(av[q].z);
            Asu[q * 4 + 3][tid] = pack2(av[q].w);
        }
        Bs[bq + 0][brow] = bv[0].x; Bs[bq + 1][brow] = bv[0].y;
        Bs[bq + 2][brow] = bv[0].z; Bs[bq + 3][brow] = bv[0].w;
        Bs[bq + 4][brow] = bv[1].x; Bs[bq + 5][brow] = bv[1].y;
        Bs[bq + 6][brow] = bv[1].z; Bs[bq + 7][brow] = bv[1].w;
        __syncthreads();
        if (kt + 16 < ks) {
#pragma unroll
            for (int q = 0; q < 4; ++q) av[q] = *(const float4*)(Ag + kt + 16 + q * 4);
            bv[0] = *(const float4*)(Bg + kt + 16);
            bv[1] = *(const float4*)(Bg + kt + 20);
        }
#pragma unroll
        for (int k = 0; k < 16; ++k) {
            ulonglong2 a01 = *(const ulonglong2*)&Asu[k][tm];
            ulonglong2 a23 = *(const ulonglong2*)&Asu[k][tm + 2];
            ulonglong2 a45 = *(const ulonglong2*)&Asu[k][tm + 4];
            ulonglong2 a67 = *(const ulonglong2*)&Asu[k][tm + 6];
            ulonglong2 b01 = *(const ulonglong2*)&Bs[k][tn];
            ulonglong2 b23 = *(const ulonglong2*)&Bs[k][tn + 4];
            ull a[8] = {a01.x, a01.y, a23.x, a23.y, a45.x, a45.y, a67.x, a67.y};
#pragma unroll
            for (int i = 0; i < 8; ++i) {
                acc[i][0] = ffma2(a[i], b01.x, acc[i][0]);
                acc[i][1] = ffma2(a[i], b01.y, acc[i][1]);
                acc[i][2] = ffma2(a[i], b23.x, acc[i][2]);
                acc[i][3] = ffma2(a[i], b23.y, acc[i][3]);
            }
        }
    }
#pragma unroll
    for (int i = 0; i < 8; ++i) {
        float* base = Cm + (size_t)(bm + tm + i) * N + bn + tn;
        ulonglong2 r0; r0.x = acc[i][0]; r0.y = acc[i][1];
        ulonglong2 r1; r1.x = acc[i][2]; r1.y = acc[i][3];
        *(ulonglong2*)(base)     = r0;
        *(ulonglong2*)(base + 4) = r1;
    }
}

// ======================================================================
// FHN: one warp per (m,h); sums the 2 gemm0 split-K partials inline.
// ======================================================================
__global__ __launch_bounds__(256) void kfhn(const float* __restrict__ sfilt) {
    const int gw = blockIdx.x * 8 + (threadIdx.x >> 5);
    const int h = gw % Hq;
    const int m = gw / Hq;
    const int k = m & 31;
    const int l = threadIdx.x & 31;
    const float* r0 = g_qkv + (size_t)m * (3 * Dq);
    const float* r1 = r0 + QKV_STRIDE;

    float q0 = r0[h * HDq + l]      + r1[h * HDq + l];
    float q1 = r0[h * HDq + l + 32] + r1[h * HDq + l + 32];
    float c0 = r0[Dq + h * HDq + l]      + r1[Dq + h * HDq + l];
    float c1 = r0[Dq + h * HDq + l + 32] + r1[Dq + h * HDq + l + 32];
    float p = q0 * c0 + q1 * c1;
#pragma unroll
    for (int o = 16; o; o >>= 1) p += __shfl_xor_sync(0xffffffffu, p, o);

    float dot  = p * 0.125f;
    float fl   = 1.f / (1.f + expf(-sfilt[h * 32 + k]));
    float stim = dot * fl;
    float as    = fabsf(stim);
    float scale = fmaxf(as, 1e-6f);
    float sn    = stim / scale;
    float gate  = 1.f / (1.f + expf(-(as - 0.5f) * 10.f));
    float I     = sn * (0.1f + 0.9f * gate);
    const float alpha = 0.08f, denom = 1.064f;
    float v = 0.f, w = 0.f;
#pragma unroll
    for (int it = 0; it < 2; ++it) {
        float dv = v - (v * v * v) / 3.0f - w + I;
        float vn = v + dv;
        float wn = (w + (vn + 0.7f) * alpha) / denom;
        v = fminf(fmaxf(vn, -3.f), 3.f);
        w = fminf(fmaxf(wn, -3.f), 3.f);
    }
    float sf = v * scale;

    float v0 = r0[2 * Dq + h * HDq + l]      + r1[2 * Dq + h * HDq + l];
    float v1 = r0[2 * Dq + h * HDq + l + 32] + r1[2 * Dq + h * HDq + l + 32];
    g_vs[(size_t)m * Dq + h * HDq + l]      = sf * v0;
    g_vs[(size_t)m * Dq + h * HDq + l + 32] = sf * v1;
}

// ======================================================================
// kyr: sum YSPLIT split-k partials -> g_ysum
// ======================================================================
__global__ void kyr() {
    const int j = blockIdx.x * 256 + threadIdx.x;
    const float4* p = (const float4*)g_y;
    float4 s = p[j];
#pragma unroll
    for (int zz = 1; zz < YSPLIT; ++zz) {
        float4 v = p[(size_t)zz * (MROWS * Dq / 4) + j];
        s.x += v.x; s.y += v.y; s.z += v.z; s.w += v.w;
    }
    ((float4*)g_ysum)[j] = s;
}

// ======================================================================
// kC (R9-exact): out[b][t,d] = sum_k basis[b][t,k] * ysum[b*32+k,d]
// ======================================================================
__global__ __launch_bounds__(128) void kC(const float* __restrict__ basis,
                                          float* __restrict__ out) {
    const int bn = blockIdx.x * 128;   // d
    const int bt = blockIdx.y * 64;    // t
    const int b  = blockIdx.z;
    const int tid = threadIdx.x;
    const int tr = tid >> 3;
    const int tc = tid & 7;

    __shared__ __align__(16) ull sA[32][66];
    __shared__ __align__(16) ull sB[32][66];

#pragma unroll
    for (int i = 0; i < 4; ++i) {
        int idx = tid + i * 128;
        int row = idx >> 3, c4 = idx & 7;
        float4 f = *(const float4*)&basis[((size_t)b * Tq + bt + row) * Kq + c4 * 4];
        sA[c4 * 4 + 0][row] = pack2(f.x);
        sA[c4 * 4 + 1][row] = pack2(f.y);
        sA[c4 * 4 + 2][row] = pack2(f.z);
        sA[c4 * 4 + 3][row] = pack2(f.w);
    }
#pragma unroll
    for (int i = 0; i < 8; ++i) {
        int idx = tid + i * 128;
        int k = idx >> 5, g = idx & 31;
        ulonglong2 v = *(const ulonglong2*)&g_ysum[(size_t)(b * Kq + k) * Dq + bn + g * 4];
        sB[k][g * 2]     = v.x;
        sB[k][g * 2 + 1] = v.y;
    }
    __syncthreads();

    ull acc[4][8];
#pragma unroll
    for (int i = 0; i < 4; ++i)
#pragma unroll
        for (int j = 0; j < 8; ++j) acc[i][j] = 0ull;

#pragma unroll
    for (int k = 0; k < 32; ++k) {
        ulonglong2 a01 = *(const ulonglong2*)&sA[k][tr * 4];
        ulonglong2 a23 = *(const ulonglong2*)&sA[k][tr * 4 + 2];
        ulonglong2 b0 = *(const ulonglong2*)&sB[k][tc * 2];
        ulonglong2 b1 = *(const ulonglong2*)&sB[k][tc * 2 + 16];
        ulonglong2 b2 = *(const ulonglong2*)&sB[k][tc * 2 + 32];
        ulonglong2 b3 = *(const ulonglong2*)&sB[k][tc * 2 + 48];
        ull a[4] = {a01.x, a01.y, a23.x, a23.y};
#pragma unroll
        for (int i = 0; i < 4; ++i) {
            acc[i][0] = ffma2(a[i], b0.x, acc[i][0]);
            acc[i][1] = ffma2(a[i], b0.y, acc[i][1]);
            acc[i][2] = ffma2(a[i], b1.x, acc[i][2]);
            acc[i][3] = ffma2(a[i], b1.y, acc[i][3]);
            acc[i][4] = ffma2(a[i], b2.x, acc[i][4]);
            acc[i][5] = ffma2(a[i], b2.y, acc[i][5]);
            acc[i][6] = ffma2(a[i], b3.x, acc[i][6]);
            acc[i][7] = ffma2(a[i], b3.y, acc[i][7]);
        }
    }

#pragma unroll
    for (int i = 0; i < 4; ++i) {
        float* base = out + ((size_t)b * Tq + bt + tr * 4 + i) * Dq + bn + tc * 4;
#pragma unroll
        for (int j = 0; j < 4; ++j) {
            ulonglong2 r; r.x = acc[i][2 * j]; r.y = acc[i][2 * j + 1];
            *(ulonglong2*)(base + j * 32) = r;
        }
    }
}

// ======================================================================
extern "C" void kernel_launch(void* const* d_in, const int* in_sizes, int n_in,
                              void* d_out, int out_size) {
    const float* x     = (const float*)d_in[0];
    const float* basis = (const float*)d_in[1];
    const float* wqkv  = (const float*)d_in[2];
    const float* wout  = (const float*)d_in[3];
    const float* sfilt = (const float*)d_in[4];
    float* out = (float*)d_out;

    kprobe<<<1, 1>>>();
    kA  <<<dim3(NSEG, Bq), 768>>>(x, basis);
    kA2 <<<(MROWS * Dq / 4) / 256, 256>>>();
    kgemm<<<dim3(2304 / 64, MROWS / 128, 2), 128>>>(wqkv, 3 * Dq, 0, 384);  // captured
    kfhn<<<3072 / 8, 256>>>(sfilt);
    kgemm<<<dim3(768 / 64, MROWS / 128, YSPLIT), 128>>>(wout, Dq, 1, 128);
    kyr <<<(MROWS * Dq / 4) / 256, 256>>>();
    kC  <<<dim3(Dq / 128, Tq / 64, Bq), 128>>>(basis, out);
}